// round 1
// baseline (speedup 1.0000x reference)
#include <cuda_runtime.h>
#include <cstdint>

// Problem shape (fixed by the dataset)
#define Bn   16
#define Tn   8192
#define Cn   128
#define NCH  16
#define CT   (Tn / NCH)   // 512 timesteps per chunk

// ---------------- device scratch (no allocations allowed) ----------------
__device__ float g_aggx [Bn * NCH * Cn];   // per-chunk local sum of x
__device__ float g_aggn [Bn * NCH * Cn];   // per-chunk local sum of (1-mask)
__device__ float g_aggsq[Bn * NCH * Cn];   // per-chunk local sum of term^2
__device__ unsigned int g_flags[2 * Bn * NCH]; // [0..255]=phase1 flags, [256..511]=phase2

// ---------------- small helpers ----------------
__device__ __forceinline__ unsigned int ld_acquire(const unsigned int* p) {
    unsigned int v;
    asm volatile("ld.acquire.gpu.u32 %0, [%1];" : "=r"(v) : "l"(p) : "memory");
    return v;
}
__device__ __forceinline__ void st_release(unsigned int* p, unsigned int v) {
    asm volatile("st.release.gpu.u32 [%0], %1;" :: "l"(p), "r"(v) : "memory");
}
__device__ __forceinline__ float frcp(float x) {
    float r; asm("rcp.approx.ftz.f32 %0, %1;" : "=f"(r) : "f"(x)); return r;
}
__device__ __forceinline__ float frsq(float x) {
    float r; asm("rsqrt.approx.ftz.f32 %0, %1;" : "=f"(r) : "f"(x)); return r;
}

// Zero the flags before every launch (graph replays included).
__global__ void revin_init_flags() {
    int i = threadIdx.x;
    if (i < 2 * Bn * NCH) g_flags[i] = 0u;
}

// ---------------- main kernel ----------------
// grid = (NCH, Bn), block = 128 threads (thread = channel c)
__global__ __launch_bounds__(128) void revin_kernel(
    const float* __restrict__ x,
    const float* __restrict__ mask,
    float* __restrict__ out)
{
    const int k = blockIdx.x;          // chunk index along T
    const int b = blockIdx.y;          // batch
    const int c = threadIdx.x;         // channel

    const int base = (b * Tn + k * CT) * Cn + c;
    const float* __restrict__ px = x    + base;
    const float* __restrict__ pm = mask + base;
    float*       __restrict__ po = out  + base;

    const int aggBase = (b * NCH + k) * Cn + c;
    unsigned int* flagsA = &g_flags[b * NCH];            // phase-1 flags for this batch
    unsigned int* flagsB = &g_flags[Bn * NCH + b * NCH]; // phase-2 flags for this batch

    // ---------------- Phase 1: local sums of x and nm ----------------
    float Lx = 0.f, Ln = 0.f;
    #pragma unroll 8
    for (int t = 0; t < CT; ++t) {
        float xv = px[t * Cn];
        float mv = pm[t * Cn];
        Lx += xv;
        Ln += 1.f - mv;
    }
    g_aggx[aggBase] = Lx;
    g_aggn[aggBase] = Ln;
    __syncthreads();
    if (threadIdx.x == 0) {
        __threadfence();
        st_release(&flagsA[k], 1u);
    }

    // Lookback: wait for all predecessors' LOCAL aggregates (no serial chain).
    if (c < k) {
        while (ld_acquire(&flagsA[c]) == 0u) __nanosleep(40);
    }
    __syncthreads();

    float ex_x = 0.f, ex_n = 0.f;
    {
        const int rowBase = b * NCH * Cn + c;
        for (int j = 0; j < k; ++j) {
            ex_x += g_aggx[rowBase + j * Cn];
            ex_n += g_aggn[rowBase + j * Cn];
        }
    }

    // ---------------- Phase 2: local sum of term^2 with true running mean ----
    float sx = ex_x, sn = ex_n, Lsq = 0.f;
    #pragma unroll 4
    for (int t = 0; t < CT; ++t) {
        float xv = px[t * Cn];
        float mv = pm[t * Cn];
        float nm = 1.f - mv;
        sx += xv;
        sn += nm;
        float nn   = (sn == 0.f) ? 1.f : sn;
        float mean = sx * frcp(nn);
        float d    = (xv - mean) * nm;
        Lsq        = fmaf(d, d, Lsq);
    }
    g_aggsq[aggBase] = Lsq;
    __syncthreads();
    if (threadIdx.x == 0) {
        __threadfence();
        st_release(&flagsB[k], 1u);
    }

    if (c < k) {
        while (ld_acquire(&flagsB[c]) == 0u) __nanosleep(40);
    }
    __syncthreads();

    float ex_sq = 0.f;
    {
        const int rowBase = b * NCH * Cn + c;
        for (int j = 0; j < k; ++j) ex_sq += g_aggsq[rowBase + j * Cn];
    }

    // ---------------- Phase 3: produce output ----------------
    sx = ex_x; sn = ex_n;
    float ssq = ex_sq;
    #pragma unroll 4
    for (int t = 0; t < CT; ++t) {
        float xv = px[t * Cn];
        float mv = pm[t * Cn];
        float nm = 1.f - mv;
        sx += xv;
        sn += nm;
        float nn   = (sn == 0.f) ? 1.f : sn;
        float rcpn = frcp(nn);
        float mean = sx * rcpn;
        float d    = (xv - mean) * nm;
        ssq        = fmaf(d, d, ssq);
        float var  = ssq * rcpn;                    // std^2
        float inv  = (var > 1e-10f) ? frsq(var) : 1.f; // std > 1e-5 <=> var > 1e-10
        float o    = (xv - mean) * inv;
        o = fminf(fmaxf(o, -100.f), 100.f);
        po[t * Cn] = o;
    }
}

// ---------------- launch ----------------
extern "C" void kernel_launch(void* const* d_in, const int* in_sizes, int n_in,
                              void* d_out, int out_size)
{
    const float* x    = (const float*)d_in[0];
    const float* mask = (const float*)d_in[1];
    float* out        = (float*)d_out;

    revin_init_flags<<<1, 2 * Bn * NCH>>>();
    dim3 grid(NCH, Bn);
    revin_kernel<<<grid, 128>>>(x, mask, out);
}

// round 2
// speedup vs baseline: 2.4714x; 2.4714x over previous
#include <cuda_runtime.h>
#include <cstdint>

// Problem shape (fixed by the dataset)
#define Bn   16
#define Tn   8192
#define Cn   128
#define NCH  64
#define CT   (Tn / NCH)   // 128 timesteps per chunk

// ---------------- device scratch (no allocations allowed) ----------------
__device__ float g_aggx [Bn * NCH * Cn];   // per-chunk local sum of x
__device__ float g_aggn [Bn * NCH * Cn];   // per-chunk local sum of (1-mask)
__device__ float g_aggsq[Bn * NCH * Cn];   // per-chunk local sum of term^2
__device__ unsigned int g_flags[2 * Bn * NCH]; // phase1 flags, phase2 flags

// ---------------- small helpers ----------------
__device__ __forceinline__ unsigned int ld_acquire(const unsigned int* p) {
    unsigned int v;
    asm volatile("ld.acquire.gpu.u32 %0, [%1];" : "=r"(v) : "l"(p) : "memory");
    return v;
}
__device__ __forceinline__ void st_release(unsigned int* p, unsigned int v) {
    asm volatile("st.release.gpu.u32 [%0], %1;" :: "l"(p), "r"(v) : "memory");
}
__device__ __forceinline__ float frcp(float x) {
    float r; asm("rcp.approx.ftz.f32 %0, %1;" : "=f"(r) : "f"(x)); return r;
}
__device__ __forceinline__ float frsq(float x) {
    float r; asm("rsqrt.approx.ftz.f32 %0, %1;" : "=f"(r) : "f"(x)); return r;
}

// Zero the flags before every launch (graph replays included).
__global__ void revin_init_flags() {
    int i = blockIdx.x * blockDim.x + threadIdx.x;
    if (i < 2 * Bn * NCH) g_flags[i] = 0u;
}

// ---------------- main kernel ----------------
// grid = (NCH, Bn), block = 128 threads (thread = channel c)
__global__ __launch_bounds__(128) void revin_kernel(
    const float* __restrict__ x,
    const float* __restrict__ mask,
    float* __restrict__ out)
{
    const int k = blockIdx.x;          // chunk index along T
    const int b = blockIdx.y;          // batch
    const int c = threadIdx.x;         // channel

    const int base = (b * Tn + k * CT) * Cn + c;
    const float* __restrict__ px = x    + base;
    const float* __restrict__ pm = mask + base;
    float*       __restrict__ po = out  + base;

    const int aggBase = (b * NCH + k) * Cn + c;
    unsigned int* flagsA = &g_flags[b * NCH];            // phase-1 flags for this batch
    unsigned int* flagsB = &g_flags[Bn * NCH + b * NCH]; // phase-2 flags for this batch

    // ---------------- Phase 1: local sums of x and nm ----------------
    float Lx = 0.f, Ln = 0.f;
    #pragma unroll 8
    for (int t = 0; t < CT; ++t) {
        float xv = px[t * Cn];
        float mv = pm[t * Cn];
        Lx += xv;
        Ln += 1.f - mv;
    }
    g_aggx[aggBase] = Lx;
    g_aggn[aggBase] = Ln;
    __syncthreads();
    if (threadIdx.x == 0) {
        __threadfence();
        st_release(&flagsA[k], 1u);
    }

    // Lookback: wait for all predecessors' LOCAL aggregates (no serial chain).
    if (c < k) {
        while (ld_acquire(&flagsA[c]) == 0u) __nanosleep(40);
    }
    __syncthreads();

    float ex_x = 0.f, ex_n = 0.f;
    {
        const int rowBase = b * NCH * Cn + c;
        #pragma unroll 4
        for (int j = 0; j < k; ++j) {
            ex_x += g_aggx[rowBase + j * Cn];
            ex_n += g_aggn[rowBase + j * Cn];
        }
    }

    // ---------------- Phase 2: local sum of term^2 with true running mean ----
    float sx = ex_x, sn = ex_n, Lsq = 0.f;
    #pragma unroll 8
    for (int t = 0; t < CT; ++t) {
        float xv = px[t * Cn];
        float mv = pm[t * Cn];
        float nm = 1.f - mv;
        sx += xv;
        sn += nm;
        float nn   = (sn == 0.f) ? 1.f : sn;
        float mean = sx * frcp(nn);
        float d    = (xv - mean) * nm;
        Lsq        = fmaf(d, d, Lsq);
    }
    g_aggsq[aggBase] = Lsq;
    __syncthreads();
    if (threadIdx.x == 0) {
        __threadfence();
        st_release(&flagsB[k], 1u);
    }

    if (c < k) {
        while (ld_acquire(&flagsB[c]) == 0u) __nanosleep(40);
    }
    __syncthreads();

    float ex_sq = 0.f;
    {
        const int rowBase = b * NCH * Cn + c;
        #pragma unroll 4
        for (int j = 0; j < k; ++j) ex_sq += g_aggsq[rowBase + j * Cn];
    }

    // ---------------- Phase 3: produce output ----------------
    sx = ex_x; sn = ex_n;
    float ssq = ex_sq;
    #pragma unroll 8
    for (int t = 0; t < CT; ++t) {
        float xv = px[t * Cn];
        float mv = pm[t * Cn];
        float nm = 1.f - mv;
        sx += xv;
        sn += nm;
        float nn   = (sn == 0.f) ? 1.f : sn;
        float rcpn = frcp(nn);
        float mean = sx * rcpn;
        float d    = (xv - mean) * nm;
        ssq        = fmaf(d, d, ssq);
        float var  = ssq * rcpn;                       // std^2
        float inv  = (var > 1e-10f) ? frsq(var) : 1.f; // std > 1e-5 <=> var > 1e-10
        float o    = (xv - mean) * inv;
        o = fminf(fmaxf(o, -100.f), 100.f);
        po[t * Cn] = o;
    }
}

// ---------------- launch ----------------
extern "C" void kernel_launch(void* const* d_in, const int* in_sizes, int n_in,
                              void* d_out, int out_size)
{
    const float* x    = (const float*)d_in[0];
    const float* mask = (const float*)d_in[1];
    float* out        = (float*)d_out;

    revin_init_flags<<<4, 512>>>();
    dim3 grid(NCH, Bn);
    revin_kernel<<<grid, 128>>>(x, mask, out);
}